// round 12
// baseline (speedup 1.0000x reference)
#include <cuda_runtime.h>
#include <cuda_bf16.h>
#include <cstdint>

#define BATCH 2
#define SEQ   2048
#define DM    1024
#define NH    16
#define DH    64
#define KS    32

#define MROWS (BATCH*SEQ)   // 4096
#define FULLM 0xffffffffu
#define NTRI  136

// ---------------- scratch ----------------------------------------------------
__device__ float g_Q [BATCH*SEQ*DM];
__device__ float g_K [BATCH*SEQ*DM];
__device__ float g_V [BATCH*SEQ*DM];
__device__ float g_HO[BATCH*SEQ*DM];
__device__ float g_WGT[BATCH*NH*SEQ*KS];
__device__ int   g_IDX[BATCH*NH*SEQ*KS];
__device__ float g_SC[(size_t)BATCH*NH*SEQ*SEQ];

__device__ __forceinline__ float neg_inf() { return __int_as_float(0xff800000); }

// ---------------- tf32 helpers -----------------------------------------------
__device__ __forceinline__ uint32_t f2tf32(float x) {
    uint32_t r; asm("cvt.rna.tf32.f32 %0, %1;" : "=r"(r) : "f"(x)); return r;
}

// c += a*b
__device__ __forceinline__ void mma_tf32(float* c,
    uint32_t a0, uint32_t a1, uint32_t a2, uint32_t a3,
    uint32_t b0, uint32_t b1)
{
    asm volatile(
        "mma.sync.aligned.m16n8k8.row.col.f32.tf32.tf32.f32 "
        "{%0,%1,%2,%3}, {%4,%5,%6,%7}, {%8,%9}, {%0,%1,%2,%3};"
        : "+f"(c[0]), "+f"(c[1]), "+f"(c[2]), "+f"(c[3])
        : "r"(a0), "r"(a1), "r"(a2), "r"(a3), "r"(b0), "r"(b1));
}

// d = a*b + 0
__device__ __forceinline__ void mma_tf32_zc(float* d,
    uint32_t a0, uint32_t a1, uint32_t a2, uint32_t a3,
    uint32_t b0, uint32_t b1)
{
    asm volatile(
        "mma.sync.aligned.m16n8k8.row.col.f32.tf32.tf32.f32 "
        "{%0,%1,%2,%3}, {%4,%5,%6,%7}, {%8,%9}, {%10,%11,%12,%13};"
        : "=f"(d[0]), "=f"(d[1]), "=f"(d[2]), "=f"(d[3])
        : "r"(a0), "r"(a1), "r"(a2), "r"(a3), "r"(b0), "r"(b1),
          "f"(0.f), "f"(0.f), "f"(0.f), "f"(0.f));
}

// ---------------- core: 128x128 tile, 512 threads, pipelined ------------------
// smem word layout per row (BK=16): two k8 groups; within group g, logical
// col c (0..7) at word g*8 + (c&3)*2 + (c>>2) -> fragment pair = one LDS.64.
#define BKT 16
#define RS  18   // row stride in words

__device__ __forceinline__ void store_hilo_tf32(
    uint32_t* H, uint32_t* L, int row, int f4, float4 v)
{
    uint32_t hx = f2tf32(v.x), hy = f2tf32(v.y), hz = f2tf32(v.z), hw = f2tf32(v.w);
    uint32_t lx = f2tf32(v.x - __uint_as_float(hx));
    uint32_t ly = f2tf32(v.y - __uint_as_float(hy));
    uint32_t lz = f2tf32(v.z - __uint_as_float(hz));
    uint32_t lw = f2tf32(v.w - __uint_as_float(hw));
    int g = f4 >> 1;
    int base = row * RS + g * 8 + (f4 & 1);
    H[base + 0] = hx; H[base + 2] = hy; H[base + 4] = hz; H[base + 6] = hw;
    L[base + 0] = lx; L[base + 2] = ly; L[base + 4] = lz; L[base + 6] = lw;
}

__device__ __forceinline__ void gemm_tile_tf32(
    const float* __restrict__ A, int lda,
    const float* __restrict__ B, int ldb,
    int Kdim,
    float* __restrict__ C, int ldc,
    const float* __restrict__ bias, float scale)
{
    __shared__ __align__(16) uint32_t AsH[128 * RS];
    __shared__ __align__(16) uint32_t AsL[128 * RS];
    __shared__ __align__(16) uint32_t BsH[128 * RS];
    __shared__ __align__(16) uint32_t BsL[128 * RS];

    const int tid  = threadIdx.x;
    const int lane = tid & 31, w = tid >> 5;
    const int wm = w >> 2, wn = w & 3;          // 4 x 4 warp grid, tile 32x32
    const int lr = lane >> 2, lc = lane & 3;

    float acc[2][4][4];
#pragma unroll
    for (int mt = 0; mt < 2; mt++)
#pragma unroll
        for (int nt = 0; nt < 4; nt++)
#pragma unroll
            for (int j = 0; j < 4; j++) acc[mt][nt][j] = 0.f;

    const int srow = tid >> 2, sf4 = tid & 3;   // staging: 1 float4/matrix/thread
    const float* Ap = A + (size_t)srow * lda + sf4 * 4;
    const float* Bp = B + (size_t)srow * ldb + sf4 * 4;

    // preload k-tile 0
    float4 pa = *(const float4*)(Ap);
    float4 pb = *(const float4*)(Bp);

    const int nk = Kdim / BKT;
    for (int kt = 0; kt < nk; kt++) {
        store_hilo_tf32(AsH, AsL, srow, sf4, pa);
        store_hilo_tf32(BsH, BsL, srow, sf4, pb);
        __syncthreads();

        if (kt + 1 < nk) {                       // prefetch next tile
            pa = *(const float4*)(Ap + (kt + 1) * BKT);
            pb = *(const float4*)(Bp + (kt + 1) * BKT);
        }

#pragma unroll
        for (int kg = 0; kg < 2; kg++) {
            const int woff = kg * 8 + 2 * lc;
            uint32_t bh[4][2], bl[4][2];
#pragma unroll
            for (int nt = 0; nt < 4; nt++) {
                int col = wn * 32 + nt * 8 + lr;
                uint64_t hv = *(const uint64_t*)&BsH[col * RS + woff];
                uint64_t lv = *(const uint64_t*)&BsL[col * RS + woff];
                bh[nt][0] = (uint32_t)hv; bh[nt][1] = (uint32_t)(hv >> 32);
                bl[nt][0] = (uint32_t)lv; bl[nt][1] = (uint32_t)(lv >> 32);
            }
#pragma unroll
            for (int mt = 0; mt < 2; mt++) {
                int r0 = wm * 32 + mt * 16 + lr;
                uint64_t h0 = *(const uint64_t*)&AsH[r0 * RS + woff];
                uint64_t h1 = *(const uint64_t*)&AsH[(r0 + 8) * RS + woff];
                uint64_t l0 = *(const uint64_t*)&AsL[r0 * RS + woff];
                uint64_t l1 = *(const uint64_t*)&AsL[(r0 + 8) * RS + woff];
                uint32_t ah0 = (uint32_t)h0, ah2 = (uint32_t)(h0 >> 32);
                uint32_t ah1 = (uint32_t)h1, ah3 = (uint32_t)(h1 >> 32);
                uint32_t al0 = (uint32_t)l0, al2 = (uint32_t)(l0 >> 32);
                uint32_t al1 = (uint32_t)l1, al3 = (uint32_t)(l1 >> 32);
#pragma unroll
                for (int nt = 0; nt < 4; nt++) {
                    // short tensor-core chain + RN register drain (proven 1e-6)
                    float ck[4];
                    mma_tf32_zc(ck, ah0, ah1, ah2, ah3, bh[nt][0], bh[nt][1]); // h*h
                    mma_tf32  (ck, ah0, ah1, ah2, ah3, bl[nt][0], bl[nt][1]);  // h*l
                    mma_tf32  (ck, al0, al1, al2, al3, bh[nt][0], bh[nt][1]);  // l*h
                    acc[mt][nt][0] += ck[0];
                    acc[mt][nt][1] += ck[1];
                    acc[mt][nt][2] += ck[2];
                    acc[mt][nt][3] += ck[3];
                }
            }
        }
        __syncthreads();
    }

#pragma unroll
    for (int mt = 0; mt < 2; mt++) {
        int r0 = wm * 32 + mt * 16 + lr;
#pragma unroll
        for (int nt = 0; nt < 4; nt++) {
            int cc = wn * 32 + nt * 8 + lc * 2;
            float b0v = bias ? bias[cc]     : 0.f;
            float b1v = bias ? bias[cc + 1] : 0.f;
            float* c0p = C + (size_t)r0 * ldc + cc;
            float* c1p = C + (size_t)(r0 + 8) * ldc + cc;
            *(float2*)c0p = make_float2(acc[mt][nt][0] * scale + b0v,
                                        acc[mt][nt][1] * scale + b1v);
            *(float2*)c1p = make_float2(acc[mt][nt][2] * scale + b0v,
                                        acc[mt][nt][3] * scale + b1v);
        }
    }
}

// ---------------- projection GEMM: C = A @ W^T + bias ------------------------
__global__ __launch_bounds__(512) void gemm_kernel(
    const float* __restrict__ A, const float* __restrict__ W,
    const float* __restrict__ bias, float* __restrict__ C,
    int M, int N, int K)
{
    int bm = blockIdx.y * 128, bn = blockIdx.x * 128;
    gemm_tile_tf32(A + (size_t)bm * K, K,
                   W + (size_t)bn * K, K,
                   K,
                   C + (size_t)bm * N + bn, N,
                   bias + bn, 1.f);
}

// ---------------- score GEMM: S = (Q @ K^T)/8, lower-triangular tiles --------
__global__ __launch_bounds__(512) void score_kernel(
    const float* __restrict__ Q, const float* __restrict__ Kg,
    float* __restrict__ SC)
{
    const int t = blockIdx.x;
    const int h = blockIdx.y, b = blockIdx.z;
    int qt = (int)((sqrtf(8.f * t + 1.f) - 1.f) * 0.5f);
    while ((qt + 1) * (qt + 2) / 2 <= t) qt++;
    while (qt * (qt + 1) / 2 > t) qt--;
    int kt = t - qt * (qt + 1) / 2;

    const float* Qb = Q  + (size_t)b * SEQ * DM + h * DH;
    const float* Kb = Kg + (size_t)b * SEQ * DM + h * DH;
    float* Sb = SC + (((size_t)b * NH + h) * SEQ) * SEQ;

    gemm_tile_tf32(Qb + (size_t)qt * 128 * DM, DM,
                   Kb + (size_t)kt * 128 * DM, DM,
                   DH,
                   Sb + (size_t)qt * 128 * SEQ + kt * 128, SEQ,
                   nullptr, 0.125f);
}

// ---------------- selection: streaming top-32 + softmax + AV -----------------
__global__ __launch_bounds__(256) void select_kernel(
    const float* __restrict__ SC, const float* __restrict__ Vg,
    float* __restrict__ HO, float* __restrict__ WGT, int* __restrict__ IDX)
{
    const int h = blockIdx.y, b = blockIdx.z;
    const int tid = threadIdx.x;
    const int lane = tid & 31, wid = tid >> 5;
    const int q = blockIdx.x * 8 + wid;
    const float NEG = neg_inf();

    const float* row = SC + ((((size_t)b*NH + h)*SEQ) + q) * SEQ;

    float sv = NEG;
    int   si = 0x7fffffff;

    const int nb = (q + 32) >> 5;
    for (int bi = 0; bi < nb; bi++) {
        int k = (bi << 5) + lane;
        float v = NEG; int ii = 0x7fffffff;
        if (k <= q) { v = row[k]; ii = k; }

        float minv = __shfl_sync(FULLM, sv, 31);
        int   mini = __shfl_sync(FULLM, si, 31);
        bool contend = (v > minv) || (v == minv && v != NEG && ii < mini);
        unsigned m = __ballot_sync(FULLM, contend);
        while (m) {
            int src = __ffs(m) - 1; m &= m - 1;
            float nv = __shfl_sync(FULLM, v,  src);
            int   ni = __shfl_sync(FULLM, ii, src);
            bool better = (sv > nv) || (sv == nv && si < ni);
            unsigned bm2 = __ballot_sync(FULLM, better);
            int p = __popc(bm2);
            float upv = __shfl_up_sync(FULLM, sv, 1);
            int   upi = __shfl_up_sync(FULLM, si, 1);
            if (lane == p)      { sv = nv;  si = ni;  }
            else if (lane > p)  { sv = upv; si = upi; }
        }
    }

    bool valid = (sv != NEG);
    float mx = __shfl_sync(FULLM, sv, 0);
    float e = valid ? expf(sv - mx) : 0.f;
    float tot = e;
#pragma unroll
    for (int o = 16; o; o >>= 1) tot += __shfl_xor_sync(FULLM, tot, o);
    float w = e / tot;
    int iw = valid ? si : -1;

    size_t off = ((((size_t)b*NH + h)*SEQ) + (size_t)q) * KS + lane;
    WGT[off] = w;
    IDX[off] = iw;

    const float* Vb = Vg + (size_t)b*SEQ*DM + h*DH;
    float acc0 = 0.f, acc1 = 0.f;
#pragma unroll
    for (int j = 0; j < KS; j++) {
        float wj = __shfl_sync(FULLM, w, j);
        int   ij = __shfl_sync(FULLM, iw, j);
        if (ij >= 0) {
            const float* vr = Vb + (size_t)ij * DM;
            acc0 += wj * vr[lane];
            acc1 += wj * vr[lane + 32];
        }
    }
    float* out = HO + ((size_t)(b*SEQ + q)) * DM + h*DH;
    out[lane]      = acc0;
    out[lane + 32] = acc1;
}

// ---------------- mean over heads -> dense [B, SEQ, SEQ] ---------------------
__global__ __launch_bounds__(256) void mean_kernel(
    const float* __restrict__ WGT, const int* __restrict__ IDX,
    float* __restrict__ out_attn)
{
    __shared__ float row[SEQ];
    const int q = blockIdx.x, b = blockIdx.y;
    const int tid = threadIdx.x;
    for (int i = tid; i < SEQ; i += 256) row[i] = 0.f;
    __syncthreads();
    for (int h = 0; h < NH; h++) {
        if (tid < KS) {
            size_t off = ((((size_t)b*NH + h)*SEQ) + q) * KS + tid;
            float w = WGT[off];
            int k = IDX[off];
            if (k >= 0 && w > 0.f) row[k] += w * (1.0f / NH);
        }
        __syncthreads();
    }
    float* o = out_attn + ((size_t)b*SEQ + q) * SEQ;
    for (int i = tid; i < SEQ; i += 256) o[i] = row[i];
}

// ---------------- launch -----------------------------------------------------
extern "C" void kernel_launch(void* const* d_in, const int* in_sizes, int n_in,
                              void* d_out, int out_size)
{
    const float* x  = (const float*)d_in[0];
    const float* Wq = (const float*)d_in[1];
    const float* bq = (const float*)d_in[2];
    const float* Wk = (const float*)d_in[3];
    const float* bk = (const float*)d_in[4];
    const float* Wv = (const float*)d_in[5];
    const float* bv = (const float*)d_in[6];
    const float* Wo = (const float*)d_in[7];
    const float* bo = (const float*)d_in[8];

    float *Qp, *Kp, *Vp, *HOp, *Wp, *Sp; int* Ip;
    cudaGetSymbolAddress((void**)&Qp,  g_Q);
    cudaGetSymbolAddress((void**)&Kp,  g_K);
    cudaGetSymbolAddress((void**)&Vp,  g_V);
    cudaGetSymbolAddress((void**)&HOp, g_HO);
    cudaGetSymbolAddress((void**)&Wp,  g_WGT);
    cudaGetSymbolAddress((void**)&Ip,  g_IDX);
    cudaGetSymbolAddress((void**)&Sp,  g_SC);

    dim3 ggrid(DM / 128, MROWS / 128);   // (8, 32)

    gemm_kernel<<<ggrid, 512>>>(x, Wq, bq, Qp, MROWS, DM, DM);
    gemm_kernel<<<ggrid, 512>>>(x, Wk, bk, Kp, MROWS, DM, DM);
    gemm_kernel<<<ggrid, 512>>>(x, Wv, bv, Vp, MROWS, DM, DM);

    score_kernel<<<dim3(NTRI, NH, BATCH), 512>>>(Qp, Kp, Sp);
    select_kernel<<<dim3(SEQ / 8, NH, BATCH), 256>>>(Sp, Vp, HOp, Wp, Ip);

    float* yout = (float*)d_out;
    gemm_kernel<<<ggrid, 512>>>(HOp, Wo, bo, yout, MROWS, DM, DM);

    size_t ysz = (size_t)BATCH * SEQ * DM;
    size_t asz = (size_t)BATCH * SEQ * SEQ;
    if ((size_t)out_size >= ysz + asz) {
        mean_kernel<<<dim3(SEQ, BATCH), 256>>>(Wp, Ip, (float*)d_out + ysz);
    }
}

// round 13
// speedup vs baseline: 1.9506x; 1.9506x over previous
#include <cuda_runtime.h>
#include <cuda_bf16.h>

#define BATCH 2
#define SEQ   2048
#define DM    1024
#define NH    16
#define DH    64
#define KS    32

#define MROWS (BATCH*SEQ)   // 4096
#define FULLM 0xffffffffu
#define NTILE 16
#define NTRI  136

// ---------------- scratch ----------------------------------------------------
__device__ float g_Q [BATCH*SEQ*DM];
__device__ float g_K [BATCH*SEQ*DM];
__device__ float g_V [BATCH*SEQ*DM];
__device__ float g_HO[BATCH*SEQ*DM];
__device__ float g_WGT[BATCH*NH*SEQ*KS];
__device__ int   g_IDX[BATCH*NH*SEQ*KS];
__device__ float g_SC[(size_t)BATCH*NH*SEQ*SEQ];

__device__ __forceinline__ float neg_inf() { return __int_as_float(0xff800000); }

// ---------------- GEMM: C[M,N] = A[M,K] @ W[N,K]^T + bias (fp32 SIMT) --------
#define BM 128
#define BN 128
#define BK 8

__global__ __launch_bounds__(256) void gemm_kernel(
    const float* __restrict__ A, const float* __restrict__ W,
    const float* __restrict__ bias, float* __restrict__ C,
    int M, int N, int K)
{
    __shared__ float As[BK][BM];
    __shared__ float Ws[BK][BN];
    int tid = threadIdx.x;
    int tx = tid & 15, ty = tid >> 4;
    int bm = blockIdx.y * BM, bn = blockIdx.x * BN;

    float acc[8][8];
#pragma unroll
    for (int i = 0; i < 8; i++)
#pragma unroll
        for (int j = 0; j < 8; j++) acc[i][j] = 0.f;

    int lr = tid >> 1;            // 0..127
    int lc = (tid & 1) * 4;       // 0 or 4

    for (int k0 = 0; k0 < K; k0 += BK) {
        float4 av = *(const float4*)(A + (size_t)(bm + lr) * K + k0 + lc);
        float4 wv = *(const float4*)(W + (size_t)(bn + lr) * K + k0 + lc);
        As[lc+0][lr] = av.x; As[lc+1][lr] = av.y; As[lc+2][lr] = av.z; As[lc+3][lr] = av.w;
        Ws[lc+0][lr] = wv.x; Ws[lc+1][lr] = wv.y; Ws[lc+2][lr] = wv.z; Ws[lc+3][lr] = wv.w;
        __syncthreads();
#pragma unroll
        for (int kk = 0; kk < BK; kk++) {
            float4 a0 = *(const float4*)&As[kk][ty*4];
            float4 a1 = *(const float4*)&As[kk][64 + ty*4];
            float4 w0 = *(const float4*)&Ws[kk][tx*4];
            float4 w1 = *(const float4*)&Ws[kk][64 + tx*4];
            float a[8] = {a0.x,a0.y,a0.z,a0.w,a1.x,a1.y,a1.z,a1.w};
            float w[8] = {w0.x,w0.y,w0.z,w0.w,w1.x,w1.y,w1.z,w1.w};
#pragma unroll
            for (int i = 0; i < 8; i++)
#pragma unroll
                for (int j = 0; j < 8; j++)
                    acc[i][j] += a[i] * w[j];
        }
        __syncthreads();
    }

    float4 b0 = *(const float4*)(bias + bn + tx*4);
    float4 b1 = *(const float4*)(bias + bn + 64 + tx*4);
    float bb[8] = {b0.x,b0.y,b0.z,b0.w,b1.x,b1.y,b1.z,b1.w};

#pragma unroll
    for (int i = 0; i < 8; i++) {
        int m = bm + ((i < 4) ? (ty*4 + i) : (64 + ty*4 + i - 4));
        float4 o0 = make_float4(acc[i][0]+bb[0], acc[i][1]+bb[1], acc[i][2]+bb[2], acc[i][3]+bb[3]);
        float4 o1 = make_float4(acc[i][4]+bb[4], acc[i][5]+bb[5], acc[i][6]+bb[6], acc[i][7]+bb[7]);
        *(float4*)(C + (size_t)m * N + bn + tx*4)      = o0;
        *(float4*)(C + (size_t)m * N + bn + 64 + tx*4) = o1;
    }
}

// ---------------- score GEMM: S[q,k] = (Q_row_q . K_row_k) / 8 ---------------
// One block per lower-triangular 128x128 tile of one (b,h). K-dim = 64.
__global__ __launch_bounds__(256) void score_kernel(
    const float* __restrict__ Q, const float* __restrict__ Kg,
    float* __restrict__ SC)
{
    __shared__ float As[16][BM];
    __shared__ float Ws[16][BN];

    const int t = blockIdx.x;
    const int h = blockIdx.y, b = blockIdx.z;
    int qt = (int)((sqrtf(8.f * t + 1.f) - 1.f) * 0.5f);
    while ((qt + 1) * (qt + 2) / 2 <= t) qt++;
    while (qt * (qt + 1) / 2 > t) qt--;
    int kt = t - qt * (qt + 1) / 2;

    const int tid = threadIdx.x;
    const int tx = tid & 15, ty = tid >> 4;
    const int bm = qt * BM, bn = kt * BN;

    float acc[8][8];
#pragma unroll
    for (int i = 0; i < 8; i++)
#pragma unroll
        for (int j = 0; j < 8; j++) acc[i][j] = 0.f;

    const float* Qb = Q  + (size_t)b*SEQ*DM + h*DH;
    const float* Kb = Kg + (size_t)b*SEQ*DM + h*DH;

    int lr = tid >> 1;            // 0..127
    int lc = (tid & 1) * 8;       // 0 or 8

    for (int k0 = 0; k0 < DH; k0 += 16) {
        float4 a0 = *(const float4*)(Qb + (size_t)(bm + lr) * DM + k0 + lc);
        float4 a1 = *(const float4*)(Qb + (size_t)(bm + lr) * DM + k0 + lc + 4);
        float4 w0 = *(const float4*)(Kb + (size_t)(bn + lr) * DM + k0 + lc);
        float4 w1 = *(const float4*)(Kb + (size_t)(bn + lr) * DM + k0 + lc + 4);
        As[lc+0][lr]=a0.x; As[lc+1][lr]=a0.y; As[lc+2][lr]=a0.z; As[lc+3][lr]=a0.w;
        As[lc+4][lr]=a1.x; As[lc+5][lr]=a1.y; As[lc+6][lr]=a1.z; As[lc+7][lr]=a1.w;
        Ws[lc+0][lr]=w0.x; Ws[lc+1][lr]=w0.y; Ws[lc+2][lr]=w0.z; Ws[lc+3][lr]=w0.w;
        Ws[lc+4][lr]=w1.x; Ws[lc+5][lr]=w1.y; Ws[lc+6][lr]=w1.z; Ws[lc+7][lr]=w1.w;
        __syncthreads();
#pragma unroll
        for (int kk = 0; kk < 16; kk++) {
            float4 q0 = *(const float4*)&As[kk][ty*4];
            float4 q1 = *(const float4*)&As[kk][64 + ty*4];
            float4 k0v = *(const float4*)&Ws[kk][tx*4];
            float4 k1v = *(const float4*)&Ws[kk][64 + tx*4];
            float a[8] = {q0.x,q0.y,q0.z,q0.w,q1.x,q1.y,q1.z,q1.w};
            float w[8] = {k0v.x,k0v.y,k0v.z,k0v.w,k1v.x,k1v.y,k1v.z,k1v.w};
#pragma unroll
            for (int i = 0; i < 8; i++)
#pragma unroll
                for (int j = 0; j < 8; j++)
                    acc[i][j] += a[i] * w[j];
        }
        __syncthreads();
    }

    float* Sb = SC + (((size_t)b*NH + h)*SEQ) * SEQ;
#pragma unroll
    for (int i = 0; i < 8; i++) {
        int m = bm + ((i < 4) ? (ty*4 + i) : (64 + ty*4 + i - 4));
        float4 o0 = make_float4(acc[i][0]*.125f, acc[i][1]*.125f, acc[i][2]*.125f, acc[i][3]*.125f);
        float4 o1 = make_float4(acc[i][4]*.125f, acc[i][5]*.125f, acc[i][6]*.125f, acc[i][7]*.125f);
        *(float4*)(Sb + (size_t)m * SEQ + bn + tx*4)      = o0;
        *(float4*)(Sb + (size_t)m * SEQ + bn + 64 + tx*4) = o1;
    }
}

// ---------------- selection: streaming top-32 (pipelined f4) + softmax + AV --
// One warp per query. 128 keys per step via 1 LDG.128/lane, next group
// prefetched during processing (MLP>=2 vs serialized scalar batches).
// Comparator (val desc, idx asc) is a strict total order -> selected set is
// processing-order invariant (identical to previous rounds).
__global__ __launch_bounds__(256) void select_kernel(
    const float* __restrict__ SC, const float* __restrict__ Vg,
    float* __restrict__ HO, float* __restrict__ WGT, int* __restrict__ IDX)
{
    const int h = blockIdx.y, b = blockIdx.z;
    const int tid = threadIdx.x;
    const int lane = tid & 31, wid = tid >> 5;
    const int q = blockIdx.x * 8 + wid;
    const float NEG = neg_inf();

    const float* row = SC + ((((size_t)b*NH + h)*SEQ) + q) * SEQ;

    float sv = NEG;
    int   si = 0x7fffffff;

    const int total = q + 1;
    const int ngrp = total >> 7;              // full 128-key groups

    float4 cur;
    if (ngrp > 0) cur = *(const float4*)(row + lane * 4);

    for (int g = 0; g < ngrp; g++) {
        float4 nxt;
        if (g + 1 < ngrp)
            nxt = *(const float4*)(row + (g + 1) * 128 + lane * 4);
        const int base = g * 128 + lane * 4;
#pragma unroll
        for (int j = 0; j < 4; j++) {
            float v = (j == 0) ? cur.x : (j == 1) ? cur.y : (j == 2) ? cur.z : cur.w;
            int ii = base + j;
            float minv = __shfl_sync(FULLM, sv, 31);
            int   mini = __shfl_sync(FULLM, si, 31);
            bool contend = (v > minv) || (v == minv && ii < mini);
            unsigned m = __ballot_sync(FULLM, contend);
            while (m) {
                int src = __ffs(m) - 1; m &= m - 1;
                float nv = __shfl_sync(FULLM, v,  src);
                int   ni = __shfl_sync(FULLM, ii, src);
                bool better = (nv < sv) || (nv == sv && si < ni);  // sv better than nv
                unsigned bm2 = __ballot_sync(FULLM, better);
                int p = __popc(bm2);
                float upv = __shfl_up_sync(FULLM, sv, 1);
                int   upi = __shfl_up_sync(FULLM, si, 1);
                if (lane == p)      { sv = nv;  si = ni;  }
                else if (lane > p)  { sv = upv; si = upi; }
            }
        }
        cur = nxt;
    }

    // tail: keys [ngrp*128, total)
    for (int k0 = ngrp << 7; k0 < total; k0 += 32) {
        int k = k0 + lane;
        float v = NEG; int ii = 0x7fffffff;
        if (k < total) { v = row[k]; ii = k; }

        float minv = __shfl_sync(FULLM, sv, 31);
        int   mini = __shfl_sync(FULLM, si, 31);
        bool contend = (v > minv) || (v == minv && v != NEG && ii < mini);
        unsigned m = __ballot_sync(FULLM, contend);
        while (m) {
            int src = __ffs(m) - 1; m &= m - 1;
            float nv = __shfl_sync(FULLM, v,  src);
            int   ni = __shfl_sync(FULLM, ii, src);
            bool better = (sv > nv) || (sv == nv && si < ni);
            unsigned bm2 = __ballot_sync(FULLM, better);
            int p = __popc(bm2);
            float upv = __shfl_up_sync(FULLM, sv, 1);
            int   upi = __shfl_up_sync(FULLM, si, 1);
            if (lane == p)      { sv = nv;  si = ni;  }
            else if (lane > p)  { sv = upv; si = upi; }
        }
    }

    // softmax over selected (sorted descending; lane 0 = max, finite)
    bool valid = (sv != NEG);
    float mx = __shfl_sync(FULLM, sv, 0);
    float e = valid ? expf(sv - mx) : 0.f;
    float tot = e;
#pragma unroll
    for (int o = 16; o; o >>= 1) tot += __shfl_xor_sync(FULLM, tot, o);
    float w = e / tot;
    int iw = valid ? si : -1;

    size_t off = ((((size_t)b*NH + h)*SEQ) + (size_t)q) * KS + lane;
    WGT[off] = w;
    IDX[off] = iw;

    // AV: each lane owns dims (lane, lane+32)
    const float* Vb = Vg + (size_t)b*SEQ*DM + h*DH;
    float acc0 = 0.f, acc1 = 0.f;
#pragma unroll
    for (int j = 0; j < KS; j++) {
        float wj = __shfl_sync(FULLM, w, j);
        int   ij = __shfl_sync(FULLM, iw, j);
        if (ij >= 0) {
            const float* vr = Vb + (size_t)ij * DM;
            acc0 += wj * vr[lane];
            acc1 += wj * vr[lane + 32];
        }
    }
    float* out = HO + ((size_t)(b*SEQ + q)) * DM + h*DH;
    out[lane]      = acc0;
    out[lane + 32] = acc1;
}

// ---------------- mean over heads -> dense [B, SEQ, SEQ] ---------------------
__global__ __launch_bounds__(256) void mean_kernel(
    const float* __restrict__ WGT, const int* __restrict__ IDX,
    float* __restrict__ out_attn)
{
    __shared__ float row[SEQ];
    const int q = blockIdx.x, b = blockIdx.y;
    const int tid = threadIdx.x;
    for (int i = tid; i < SEQ; i += 256) row[i] = 0.f;
    __syncthreads();
    for (int h = 0; h < NH; h++) {
        if (tid < KS) {
            size_t off = ((((size_t)b*NH + h)*SEQ) + q) * KS + tid;
            float w = WGT[off];
            int k = IDX[off];
            if (k >= 0 && w > 0.f) row[k] += w * (1.0f / NH);
        }
        __syncthreads();
    }
    float* o = out_attn + ((size_t)b*SEQ + q) * SEQ;
    for (int i = tid; i < SEQ; i += 256) o[i] = row[i];
}

// ---------------- launch -----------------------------------------------------
extern "C" void kernel_launch(void* const* d_in, const int* in_sizes, int n_in,
                              void* d_out, int out_size)
{
    const float* x  = (const float*)d_in[0];
    const float* Wq = (const float*)d_in[1];
    const float* bq = (const float*)d_in[2];
    const float* Wk = (const float*)d_in[3];
    const float* bk = (const float*)d_in[4];
    const float* Wv = (const float*)d_in[5];
    const float* bv = (const float*)d_in[6];
    const float* Wo = (const float*)d_in[7];
    const float* bo = (const float*)d_in[8];

    float *Qp, *Kp, *Vp, *HOp, *Wp, *Sp; int* Ip;
    cudaGetSymbolAddress((void**)&Qp,  g_Q);
    cudaGetSymbolAddress((void**)&Kp,  g_K);
    cudaGetSymbolAddress((void**)&Vp,  g_V);
    cudaGetSymbolAddress((void**)&HOp, g_HO);
    cudaGetSymbolAddress((void**)&Wp,  g_WGT);
    cudaGetSymbolAddress((void**)&Ip,  g_IDX);
    cudaGetSymbolAddress((void**)&Sp,  g_SC);

    dim3 ggrid(DM / BN, MROWS / BM);   // (8, 32)

    gemm_kernel<<<ggrid, 256>>>(x, Wq, bq, Qp, MROWS, DM, DM);
    gemm_kernel<<<ggrid, 256>>>(x, Wk, bk, Kp, MROWS, DM, DM);
    gemm_kernel<<<ggrid, 256>>>(x, Wv, bv, Vp, MROWS, DM, DM);

    score_kernel<<<dim3(NTRI, NH, BATCH), 256>>>(Qp, Kp, Sp);
    select_kernel<<<dim3(SEQ / 8, NH, BATCH), 256>>>(Sp, Vp, HOp, Wp, Ip);

    float* yout = (float*)d_out;
    gemm_kernel<<<ggrid, 256>>>(HOp, Wo, bo, yout, MROWS, DM, DM);

    size_t ysz = (size_t)BATCH * SEQ * DM;          // 4,194,304
    size_t asz = (size_t)BATCH * SEQ * SEQ;         // 8,388,608
    if ((size_t)out_size >= ysz + asz) {
        mean_kernel<<<dim3(SEQ, BATCH), 256>>>(Wp, Ip, (float*)d_out + ysz);
    }
}

// round 14
// speedup vs baseline: 2.1159x; 1.0847x over previous
#include <cuda_runtime.h>
#include <cuda_bf16.h>

#define BATCH 2
#define SEQ   2048
#define DM    1024
#define NH    16
#define DH    64
#define KS    32

#define MROWS (BATCH*SEQ)   // 4096
#define FULLM 0xffffffffu
#define NTILE 16
#define NTRI  136

// ---------------- scratch ----------------------------------------------------
__device__ float g_Q [BATCH*SEQ*DM];
__device__ float g_K [BATCH*SEQ*DM];
__device__ float g_V [BATCH*SEQ*DM];
__device__ float g_HO[BATCH*SEQ*DM];
__device__ float g_WGT[BATCH*NH*SEQ*KS];
__device__ int   g_IDX[BATCH*NH*SEQ*KS];
__device__ float g_SC[(size_t)BATCH*NH*SEQ*SEQ];

__device__ __forceinline__ float neg_inf() { return __int_as_float(0xff800000); }

// ---------------- GEMM: C[M,N] = A[M,K] @ W[N,K]^T + bias (fp32 SIMT) --------
// BK=16, double-buffered smem, register prefetch. Same per-thread FFMA k-order
// as the BK=8 version -> bitwise-identical results.
#define BM 128
#define BN 128
#define BK2 16

__global__ __launch_bounds__(256) void gemm_kernel(
    const float* __restrict__ A, const float* __restrict__ W,
    const float* __restrict__ bias, float* __restrict__ C,
    int M, int N, int K)
{
    __shared__ float As[2][BK2][BM];
    __shared__ float Ws[2][BK2][BN];
    const int tid = threadIdx.x;
    const int tx = tid & 15, ty = tid >> 4;
    const int bm = blockIdx.y * BM, bn = blockIdx.x * BN;

    float acc[8][8];
#pragma unroll
    for (int i = 0; i < 8; i++)
#pragma unroll
        for (int j = 0; j < 8; j++) acc[i][j] = 0.f;

    const int lr = tid >> 1;            // 0..127
    const int lc = (tid & 1) * 8;       // 0 or 8

    const float* Ap = A + (size_t)(bm + lr) * K + lc;
    const float* Wp = W + (size_t)(bn + lr) * K + lc;

    float4 pa0 = *(const float4*)(Ap);
    float4 pa1 = *(const float4*)(Ap + 4);
    float4 pw0 = *(const float4*)(Wp);
    float4 pw1 = *(const float4*)(Wp + 4);

    // store tile 0 into buffer 0
    {
        As[0][lc+0][lr]=pa0.x; As[0][lc+1][lr]=pa0.y; As[0][lc+2][lr]=pa0.z; As[0][lc+3][lr]=pa0.w;
        As[0][lc+4][lr]=pa1.x; As[0][lc+5][lr]=pa1.y; As[0][lc+6][lr]=pa1.z; As[0][lc+7][lr]=pa1.w;
        Ws[0][lc+0][lr]=pw0.x; Ws[0][lc+1][lr]=pw0.y; Ws[0][lc+2][lr]=pw0.z; Ws[0][lc+3][lr]=pw0.w;
        Ws[0][lc+4][lr]=pw1.x; Ws[0][lc+5][lr]=pw1.y; Ws[0][lc+6][lr]=pw1.z; Ws[0][lc+7][lr]=pw1.w;
    }
    __syncthreads();

    const int ntile = K / BK2;
    for (int t = 0; t < ntile; t++) {
        const int buf = t & 1;
        const bool more = (t + 1 < ntile);
        if (more) {                     // prefetch next tile into registers
            pa0 = *(const float4*)(Ap + (t + 1) * BK2);
            pa1 = *(const float4*)(Ap + (t + 1) * BK2 + 4);
            pw0 = *(const float4*)(Wp + (t + 1) * BK2);
            pw1 = *(const float4*)(Wp + (t + 1) * BK2 + 4);
        }
#pragma unroll
        for (int kk = 0; kk < BK2; kk++) {
            float4 a0 = *(const float4*)&As[buf][kk][ty*4];
            float4 a1 = *(const float4*)&As[buf][kk][64 + ty*4];
            float4 w0 = *(const float4*)&Ws[buf][kk][tx*4];
            float4 w1 = *(const float4*)&Ws[buf][kk][64 + tx*4];
            float a[8] = {a0.x,a0.y,a0.z,a0.w,a1.x,a1.y,a1.z,a1.w};
            float w[8] = {w0.x,w0.y,w0.z,w0.w,w1.x,w1.y,w1.z,w1.w};
#pragma unroll
            for (int i = 0; i < 8; i++)
#pragma unroll
                for (int j = 0; j < 8; j++)
                    acc[i][j] += a[i] * w[j];
        }
        if (more) {                     // store prefetched tile into other buffer
            const int nb = buf ^ 1;
            As[nb][lc+0][lr]=pa0.x; As[nb][lc+1][lr]=pa0.y; As[nb][lc+2][lr]=pa0.z; As[nb][lc+3][lr]=pa0.w;
            As[nb][lc+4][lr]=pa1.x; As[nb][lc+5][lr]=pa1.y; As[nb][lc+6][lr]=pa1.z; As[nb][lc+7][lr]=pa1.w;
            Ws[nb][lc+0][lr]=pw0.x; Ws[nb][lc+1][lr]=pw0.y; Ws[nb][lc+2][lr]=pw0.z; Ws[nb][lc+3][lr]=pw0.w;
            Ws[nb][lc+4][lr]=pw1.x; Ws[nb][lc+5][lr]=pw1.y; Ws[nb][lc+6][lr]=pw1.z; Ws[nb][lc+7][lr]=pw1.w;
        }
        __syncthreads();
    }

    float4 b0 = *(const float4*)(bias + bn + tx*4);
    float4 b1 = *(const float4*)(bias + bn + 64 + tx*4);
    float bb[8] = {b0.x,b0.y,b0.z,b0.w,b1.x,b1.y,b1.z,b1.w};

#pragma unroll
    for (int i = 0; i < 8; i++) {
        int m = bm + ((i < 4) ? (ty*4 + i) : (64 + ty*4 + i - 4));
        float4 o0 = make_float4(acc[i][0]+bb[0], acc[i][1]+bb[1], acc[i][2]+bb[2], acc[i][3]+bb[3]);
        float4 o1 = make_float4(acc[i][4]+bb[4], acc[i][5]+bb[5], acc[i][6]+bb[6], acc[i][7]+bb[7]);
        *(float4*)(C + (size_t)m * N + bn + tx*4)      = o0;
        *(float4*)(C + (size_t)m * N + bn + 64 + tx*4) = o1;
    }
}

// ---------------- score GEMM: S[q,k] = (Q_row_q . K_row_k) / 8 ---------------
// One block per lower-triangular 128x128 tile of one (b,h). K-dim = 64.
__global__ __launch_bounds__(256) void score_kernel(
    const float* __restrict__ Q, const float* __restrict__ Kg,
    float* __restrict__ SC)
{
    __shared__ float As[16][BM];
    __shared__ float Ws[16][BN];

    const int t = blockIdx.x;
    const int h = blockIdx.y, b = blockIdx.z;
    int qt = (int)((sqrtf(8.f * t + 1.f) - 1.f) * 0.5f);
    while ((qt + 1) * (qt + 2) / 2 <= t) qt++;
    while (qt * (qt + 1) / 2 > t) qt--;
    int kt = t - qt * (qt + 1) / 2;

    const int tid = threadIdx.x;
    const int tx = tid & 15, ty = tid >> 4;
    const int bm = qt * BM, bn = kt * BN;

    float acc[8][8];
#pragma unroll
    for (int i = 0; i < 8; i++)
#pragma unroll
        for (int j = 0; j < 8; j++) acc[i][j] = 0.f;

    const float* Qb = Q  + (size_t)b*SEQ*DM + h*DH;
    const float* Kb = Kg + (size_t)b*SEQ*DM + h*DH;

    int lr = tid >> 1;            // 0..127
    int lc = (tid & 1) * 8;       // 0 or 8

    for (int k0 = 0; k0 < DH; k0 += 16) {
        float4 a0 = *(const float4*)(Qb + (size_t)(bm + lr) * DM + k0 + lc);
        float4 a1 = *(const float4*)(Qb + (size_t)(bm + lr) * DM + k0 + lc + 4);
        float4 w0 = *(const float4*)(Kb + (size_t)(bn + lr) * DM + k0 + lc);
        float4 w1 = *(const float4*)(Kb + (size_t)(bn + lr) * DM + k0 + lc + 4);
        As[lc+0][lr]=a0.x; As[lc+1][lr]=a0.y; As[lc+2][lr]=a0.z; As[lc+3][lr]=a0.w;
        As[lc+4][lr]=a1.x; As[lc+5][lr]=a1.y; As[lc+6][lr]=a1.z; As[lc+7][lr]=a1.w;
        Ws[lc+0][lr]=w0.x; Ws[lc+1][lr]=w0.y; Ws[lc+2][lr]=w0.z; Ws[lc+3][lr]=w0.w;
        Ws[lc+4][lr]=w1.x; Ws[lc+5][lr]=w1.y; Ws[lc+6][lr]=w1.z; Ws[lc+7][lr]=w1.w;
        __syncthreads();
#pragma unroll
        for (int kk = 0; kk < 16; kk++) {
            float4 q0 = *(const float4*)&As[kk][ty*4];
            float4 q1 = *(const float4*)&As[kk][64 + ty*4];
            float4 k0v = *(const float4*)&Ws[kk][tx*4];
            float4 k1v = *(const float4*)&Ws[kk][64 + tx*4];
            float a[8] = {q0.x,q0.y,q0.z,q0.w,q1.x,q1.y,q1.z,q1.w};
            float w[8] = {k0v.x,k0v.y,k0v.z,k0v.w,k1v.x,k1v.y,k1v.z,k1v.w};
#pragma unroll
            for (int i = 0; i < 8; i++)
#pragma unroll
                for (int j = 0; j < 8; j++)
                    acc[i][j] += a[i] * w[j];
        }
        __syncthreads();
    }

    float* Sb = SC + (((size_t)b*NH + h)*SEQ) * SEQ;
#pragma unroll
    for (int i = 0; i < 8; i++) {
        int m = bm + ((i < 4) ? (ty*4 + i) : (64 + ty*4 + i - 4));
        float4 o0 = make_float4(acc[i][0]*.125f, acc[i][1]*.125f, acc[i][2]*.125f, acc[i][3]*.125f);
        float4 o1 = make_float4(acc[i][4]*.125f, acc[i][5]*.125f, acc[i][6]*.125f, acc[i][7]*.125f);
        *(float4*)(Sb + (size_t)m * SEQ + bn + tx*4)      = o0;
        *(float4*)(Sb + (size_t)m * SEQ + bn + 64 + tx*4) = o1;
    }
}

// ---------------- selection: streaming top-32 (pipelined f4) + softmax + AV --
// One warp per query. Running-min (minv/mini) cached in registers and only
// refreshed after an insertion -> fewer shfls on non-contending batches.
// Comparator is a strict total order -> selected set identical to before.
__global__ __launch_bounds__(256) void select_kernel(
    const float* __restrict__ SC, const float* __restrict__ Vg,
    float* __restrict__ HO, float* __restrict__ WGT, int* __restrict__ IDX)
{
    const int h = blockIdx.y, b = blockIdx.z;
    const int tid = threadIdx.x;
    const int lane = tid & 31, wid = tid >> 5;
    const int q = blockIdx.x * 8 + wid;
    const float NEG = neg_inf();

    const float* row = SC + ((((size_t)b*NH + h)*SEQ) + q) * SEQ;

    float sv = NEG;
    int   si = 0x7fffffff;
    float minv = NEG;
    int   mini = 0x7fffffff;

    const int total = q + 1;
    const int ngrp = total >> 7;              // full 128-key groups

    float4 cur;
    if (ngrp > 0) cur = *(const float4*)(row + lane * 4);

    for (int g = 0; g < ngrp; g++) {
        float4 nxt;
        if (g + 1 < ngrp)
            nxt = *(const float4*)(row + (g + 1) * 128 + lane * 4);
        const int base = g * 128 + lane * 4;
#pragma unroll
        for (int j = 0; j < 4; j++) {
            float v = (j == 0) ? cur.x : (j == 1) ? cur.y : (j == 2) ? cur.z : cur.w;
            int ii = base + j;
            bool contend = (v > minv) || (v == minv && ii < mini);
            unsigned m = __ballot_sync(FULLM, contend);
            if (m) {
                do {
                    int src = __ffs(m) - 1; m &= m - 1;
                    float nv = __shfl_sync(FULLM, v,  src);
                    int   ni = __shfl_sync(FULLM, ii, src);
                    bool better = (nv < sv) || (nv == sv && si < ni);  // sv better
                    unsigned bm2 = __ballot_sync(FULLM, better);
                    int p = __popc(bm2);
                    float upv = __shfl_up_sync(FULLM, sv, 1);
                    int   upi = __shfl_up_sync(FULLM, si, 1);
                    if (lane == p)      { sv = nv;  si = ni;  }
                    else if (lane > p)  { sv = upv; si = upi; }
                } while (m);
                minv = __shfl_sync(FULLM, sv, 31);
                mini = __shfl_sync(FULLM, si, 31);
            }
        }
        cur = nxt;
    }

    // tail: keys [ngrp*128, total)
    for (int k0 = ngrp << 7; k0 < total; k0 += 32) {
        int k = k0 + lane;
        float v = NEG; int ii = 0x7fffffff;
        if (k < total) { v = row[k]; ii = k; }

        bool contend = (v > minv) || (v == minv && v != NEG && ii < mini);
        unsigned m = __ballot_sync(FULLM, contend);
        if (m) {
            do {
                int src = __ffs(m) - 1; m &= m - 1;
                float nv = __shfl_sync(FULLM, v,  src);
                int   ni = __shfl_sync(FULLM, ii, src);
                bool better = (sv > nv) || (sv == nv && si < ni);
                unsigned bm2 = __ballot_sync(FULLM, better);
                int p = __popc(bm2);
                float upv = __shfl_up_sync(FULLM, sv, 1);
                int   upi = __shfl_up_sync(FULLM, si, 1);
                if (lane == p)      { sv = nv;  si = ni;  }
                else if (lane > p)  { sv = upv; si = upi; }
            } while (m);
            minv = __shfl_sync(FULLM, sv, 31);
            mini = __shfl_sync(FULLM, si, 31);
        }
    }

    // softmax over selected (sorted descending; lane 0 = max, finite)
    bool valid = (sv != NEG);
    float mx = __shfl_sync(FULLM, sv, 0);
    float e = valid ? expf(sv - mx) : 0.f;
    float tot = e;
#pragma unroll
    for (int o = 16; o; o >>= 1) tot += __shfl_xor_sync(FULLM, tot, o);
    float w = e / tot;
    int iw = valid ? si : -1;

    size_t off = ((((size_t)b*NH + h)*SEQ) + (size_t)q) * KS + lane;
    WGT[off] = w;
    IDX[off] = iw;

    // AV: each lane owns dims (lane, lane+32)
    const float* Vb = Vg + (size_t)b*SEQ*DM + h*DH;
    float acc0 = 0.f, acc1 = 0.f;
#pragma unroll
    for (int j = 0; j < KS; j++) {
        float wj = __shfl_sync(FULLM, w, j);
        int   ij = __shfl_sync(FULLM, iw, j);
        if (ij >= 0) {
            const float* vr = Vb + (size_t)ij * DM;
            acc0 += wj * vr[lane];
            acc1 += wj * vr[lane + 32];
        }
    }
    float* out = HO + ((size_t)(b*SEQ + q)) * DM + h*DH;
    out[lane]      = acc0;
    out[lane + 32] = acc1;
}

// ---------------- mean over heads -> dense [B, SEQ, SEQ] ---------------------
__global__ __launch_bounds__(256) void mean_kernel(
    const float* __restrict__ WGT, const int* __restrict__ IDX,
    float* __restrict__ out_attn)
{
    __shared__ float row[SEQ];
    const int q = blockIdx.x, b = blockIdx.y;
    const int tid = threadIdx.x;
    for (int i = tid; i < SEQ; i += 256) row[i] = 0.f;
    __syncthreads();
    for (int h = 0; h < NH; h++) {
        if (tid < KS) {
            size_t off = ((((size_t)b*NH + h)*SEQ) + q) * KS + tid;
            float w = WGT[off];
            int k = IDX[off];
            if (k >= 0 && w > 0.f) row[k] += w * (1.0f / NH);
        }
        __syncthreads();
    }
    float* o = out_attn + ((size_t)b*SEQ + q) * SEQ;
    for (int i = tid; i < SEQ; i += 256) o[i] = row[i];
}

// ---------------- launch -----------------------------------------------------
extern "C" void kernel_launch(void* const* d_in, const int* in_sizes, int n_in,
                              void* d_out, int out_size)
{
    const float* x  = (const float*)d_in[0];
    const float* Wq = (const float*)d_in[1];
    const float* bq = (const float*)d_in[2];
    const float* Wk = (const float*)d_in[3];
    const float* bk = (const float*)d_in[4];
    const float* Wv = (const float*)d_in[5];
    const float* bv = (const float*)d_in[6];
    const float* Wo = (const float*)d_in[7];
    const float* bo = (const float*)d_in[8];

    float *Qp, *Kp, *Vp, *HOp, *Wp, *Sp; int* Ip;
    cudaGetSymbolAddress((void**)&Qp,  g_Q);
    cudaGetSymbolAddress((void**)&Kp,  g_K);
    cudaGetSymbolAddress((void**)&Vp,  g_V);
    cudaGetSymbolAddress((void**)&HOp, g_HO);
    cudaGetSymbolAddress((void**)&Wp,  g_WGT);
    cudaGetSymbolAddress((void**)&Ip,  g_IDX);
    cudaGetSymbolAddress((void**)&Sp,  g_SC);

    dim3 ggrid(DM / BN, MROWS / BM);   // (8, 32)

    gemm_kernel<<<ggrid, 256>>>(x, Wq, bq, Qp, MROWS, DM, DM);
    gemm_kernel<<<ggrid, 256>>>(x, Wk, bk, Kp, MROWS, DM, DM);
    gemm_kernel<<<ggrid, 256>>>(x, Wv, bv, Vp, MROWS, DM, DM);

    score_kernel<<<dim3(NTRI, NH, BATCH), 256>>>(Qp, Kp, Sp);
    select_kernel<<<dim3(SEQ / 8, NH, BATCH), 256>>>(Sp, Vp, HOp, Wp, Ip);

    float* yout = (float*)d_out;
    gemm_kernel<<<ggrid, 256>>>(HOp, Wo, bo, yout, MROWS, DM, DM);

    size_t ysz = (size_t)BATCH * SEQ * DM;          // 4,194,304
    size_t asz = (size_t)BATCH * SEQ * SEQ;         // 8,388,608
    if ((size_t)out_size >= ysz + asz) {
        mean_kernel<<<dim3(SEQ, BATCH), 256>>>(Wp, Ip, (float*)d_out + ysz);
    }
}